// round 9
// baseline (speedup 1.0000x reference)
#include <cuda_runtime.h>

// DenseQConv1D analytic collapse (exact):
//   out[b,c,l] = cos(theta[c,0]) * (S_even - S_odd) / max(S_total, 1e-24)
//   with S_* = windowed 8-tap sums of a[b,l] = sum_cin x[b,cin,l]^2.
// Derivation: out = s^T (E R) S (E R)^T s ; R S R^T = H(theta0) (x) I^8 ;
// E = CNOT-ring permutation (linear over GF(2)); conjugated M_c is
// diag(+/-cos(theta[c,0])) on the 128-dim patch support, sign = (-1)^(j&1).
//
// R9: single-ratio epilogue — 64 CTAs x 512 threads (4-way channel-split
//     load phase as R8), but the window ratio r[lidx] is computed ONCE by
//     128 threads into smem (instead of 4x redundantly, 32 LDS/thread),
//     then all 512 threads remap to (channel, 4-l-group) and store 4
//     consecutive-l scalars each. Wall is at the graph-replay floor
//     (~6.6us); this trims the cold-clock critical path further.

#define BB 8
#define C_IN 16
#define C_OUT 16
#define LL 1024
#define KK 8
#define L_OUT (LL - KK + 1)   // 1017
#define TL 128                // l-positions per CTA
#define NT 512                // threads per CTA
#define NQ 9

__global__ __launch_bounds__(NT) void DenseQConv1D_84542136255139_kernel(
    const float* __restrict__ x,      // [B, C_IN, L]
    const float* __restrict__ theta,  // [C_OUT, NQ]
    float* __restrict__ out)          // [B, C_OUT, L_OUT]
{
    __shared__ float p[4][TL + KK];   // per-quarter channel-reduced squares + halo
    __shared__ float rbuf[TL];        // window ratio per l
    __shared__ float cosv[C_OUT];

    const int b    = blockIdx.y;
    const int l0   = blockIdx.x * TL;
    const int tid  = threadIdx.x;
    const int lidx = tid & (TL - 1);  // l within tile (phase 1 role)
    const int q    = tid >> 7;        // quarter: channels 4q .. 4q+3

    if (tid < C_OUT) cosv[tid] = cosf(theta[tid * NQ]);

    // Phase 1: p[q][lidx] = sum over this quarter's 4 channels of x^2.
    // Halo values computed in the same instruction stream (single load flight).
    {
        const int l = l0 + lidx;                       // always < LL
        const bool halo_ok = (lidx < KK - 1) && (l + TL < LL);
        const float* xb = x + (size_t)b * (C_IN * LL) + q * (4 * LL) + l;

        float v0 = xb[0 * LL];
        float v1 = xb[1 * LL];
        float v2 = xb[2 * LL];
        float v3 = xb[3 * LL];
        float w0 = halo_ok ? xb[0 * LL + TL] : 0.f;
        float w1 = halo_ok ? xb[1 * LL + TL] : 0.f;
        float w2 = halo_ok ? xb[2 * LL + TL] : 0.f;
        float w3 = halo_ok ? xb[3 * LL + TL] : 0.f;

        float m01 = fmaf(v0, v0, v1 * v1);
        float m23 = fmaf(v2, v2, v3 * v3);
        float h01 = fmaf(w0, w0, w1 * w1);
        float h23 = fmaf(w2, w2, w3 * w3);

        p[q][lidx] = m01 + m23;
        if (lidx < KK - 1) p[q][lidx + TL] = h01 + h23;
    }
    __syncthreads();

    // Phase 2a: threads 0..127 compute the window ratio once.
    if (tid < TL) {
        float a0 = (p[0][tid]     + p[1][tid])     + (p[2][tid]     + p[3][tid]);
        float a1 = (p[0][tid + 1] + p[1][tid + 1]) + (p[2][tid + 1] + p[3][tid + 1]);
        float a2 = (p[0][tid + 2] + p[1][tid + 2]) + (p[2][tid + 2] + p[3][tid + 2]);
        float a3 = (p[0][tid + 3] + p[1][tid + 3]) + (p[2][tid + 3] + p[3][tid + 3]);
        float a4 = (p[0][tid + 4] + p[1][tid + 4]) + (p[2][tid + 4] + p[3][tid + 4]);
        float a5 = (p[0][tid + 5] + p[1][tid + 5]) + (p[2][tid + 5] + p[3][tid + 5]);
        float a6 = (p[0][tid + 6] + p[1][tid + 6]) + (p[2][tid + 6] + p[3][tid + 6]);
        float a7 = (p[0][tid + 7] + p[1][tid + 7]) + (p[2][tid + 7] + p[3][tid + 7]);
        float se = (a0 + a2) + (a4 + a6);
        float so = (a1 + a3) + (a5 + a7);
        rbuf[tid] = __fdividef(se - so, fmaxf(se + so, 1e-24f));
    }
    __syncthreads();

    // Phase 2b: remap 512 threads -> (channel, 4-l group); each thread stores
    // 4 consecutive l positions of one channel (coalesced across the group).
    {
        const int c  = tid >> 5;                 // 0..15
        const int g  = (tid & 31) * 4;           // l-group start within tile
        const int l  = l0 + g;
        const float cv = cosv[c];
        float* ob = out + (size_t)b * (C_OUT * L_OUT) + (size_t)c * L_OUT + l;
        const float r0 = rbuf[g + 0];
        const float r1 = rbuf[g + 1];
        const float r2 = rbuf[g + 2];
        const float r3 = rbuf[g + 3];
        if (l + 3 < L_OUT) {
            ob[0] = cv * r0;
            ob[1] = cv * r1;
            ob[2] = cv * r2;
            ob[3] = cv * r3;
        } else {
            if (l + 0 < L_OUT) ob[0] = cv * r0;
            if (l + 1 < L_OUT) ob[1] = cv * r1;
            if (l + 2 < L_OUT) ob[2] = cv * r2;
            if (l + 3 < L_OUT) ob[3] = cv * r3;
        }
    }
}

extern "C" void kernel_launch(void* const* d_in, const int* in_sizes, int n_in,
                              void* d_out, int out_size)
{
    // Resolve inputs by element count (robust to metadata ordering):
    //   x: 131072, theta: 144, entangle: 262144 (unused)
    const float* x = nullptr;
    const float* theta = nullptr;
    for (int i = 0; i < n_in; ++i) {
        if (in_sizes[i] == BB * C_IN * LL)      x     = (const float*)d_in[i];
        else if (in_sizes[i] == C_OUT * NQ)     theta = (const float*)d_in[i];
    }

    dim3 grid((L_OUT + TL - 1) / TL, BB);   // 8 x 8 = 64 CTAs
    DenseQConv1D_84542136255139_kernel<<<grid, NT>>>(x, theta, (float*)d_out);
}

// round 10
// speedup vs baseline: 1.0591x; 1.0591x over previous
#include <cuda_runtime.h>

// DenseQConv1D analytic collapse (exact):
//   out[b,c,l] = cos(theta[c,0]) * (S_even - S_odd) / max(S_total, 1e-24)
//   with S_* = windowed 8-tap sums of a[b,l] = sum_cin x[b,cin,l]^2.
// Derivation: out = s^T (E R) S (E R)^T s ; R S R^T = H(theta0) (x) I^8 ;
// E = CNOT-ring permutation (linear over GF(2)); conjugated M_c is
// diag(+/-cos(theta[c,0])) on the 128-dim patch support, sign = (-1)^(j&1).
//
// FINAL (= R8): 4-way channel split, 64 CTAs x 512 threads, single barrier.
//   Session conclusion: wall = max(graph-replay floor ~6.62us, kernel@NAT).
//   Kernel@NAT ~2.5us — well under the floor. R5 (8 CTAs) and R9 (2-barrier
//   serialized epilogue) both regressed by lengthening the critical path;
//   this shape is the verified tied-minimum (6.624us, rel_err 4.9e-7).

#define BB 8
#define C_IN 16
#define C_OUT 16
#define LL 1024
#define KK 8
#define L_OUT (LL - KK + 1)   // 1017
#define TL 128                // l-positions per CTA
#define NT 512                // threads per CTA (4 quarters x TL)
#define NQ 9

__global__ __launch_bounds__(NT) void DenseQConv1D_84542136255139_kernel(
    const float* __restrict__ x,      // [B, C_IN, L]
    const float* __restrict__ theta,  // [C_OUT, NQ]
    float* __restrict__ out)          // [B, C_OUT, L_OUT]
{
    __shared__ float p[4][TL + KK];   // per-quarter channel-reduced squares + halo
    __shared__ float cosv[C_OUT];

    const int b    = blockIdx.y;
    const int l0   = blockIdx.x * TL;
    const int tid  = threadIdx.x;
    const int lidx = tid & (TL - 1);  // l within tile
    const int q    = tid >> 7;        // quarter: channels 4q .. 4q+3

    if (tid < C_OUT) cosv[tid] = cosf(theta[tid * NQ]);

    // Phase 1: p[q][lidx] = sum over this quarter's 4 channels of x^2.
    // Halo values computed in the same instruction stream (single load flight).
    {
        const int l = l0 + lidx;                       // always < LL
        const bool halo_ok = (lidx < KK - 1) && (l + TL < LL);
        const float* xb = x + (size_t)b * (C_IN * LL) + q * (4 * LL) + l;

        float v0 = xb[0 * LL];
        float v1 = xb[1 * LL];
        float v2 = xb[2 * LL];
        float v3 = xb[3 * LL];
        float w0 = halo_ok ? xb[0 * LL + TL] : 0.f;
        float w1 = halo_ok ? xb[1 * LL + TL] : 0.f;
        float w2 = halo_ok ? xb[2 * LL + TL] : 0.f;
        float w3 = halo_ok ? xb[3 * LL + TL] : 0.f;

        float m01 = fmaf(v0, v0, v1 * v1);
        float m23 = fmaf(v2, v2, v3 * v3);
        float h01 = fmaf(w0, w0, w1 * w1);
        float h23 = fmaf(w2, w2, w3 * w3);

        p[q][lidx] = m01 + m23;
        if (lidx < KK - 1) p[q][lidx + TL] = h01 + h23;
    }
    __syncthreads();

    // Phase 2: all quarters redundantly form the window ratio (32 pipelined
    // LDS — redundant wide parallelism beats a serialized compute-once
    // epilogue, per R9), then each stores its own 4 output channels.
    const int l = l0 + lidx;
    if (l < L_OUT) {
        float a0 = (p[0][lidx]     + p[1][lidx])     + (p[2][lidx]     + p[3][lidx]);
        float a1 = (p[0][lidx + 1] + p[1][lidx + 1]) + (p[2][lidx + 1] + p[3][lidx + 1]);
        float a2 = (p[0][lidx + 2] + p[1][lidx + 2]) + (p[2][lidx + 2] + p[3][lidx + 2]);
        float a3 = (p[0][lidx + 3] + p[1][lidx + 3]) + (p[2][lidx + 3] + p[3][lidx + 3]);
        float a4 = (p[0][lidx + 4] + p[1][lidx + 4]) + (p[2][lidx + 4] + p[3][lidx + 4]);
        float a5 = (p[0][lidx + 5] + p[1][lidx + 5]) + (p[2][lidx + 5] + p[3][lidx + 5]);
        float a6 = (p[0][lidx + 6] + p[1][lidx + 6]) + (p[2][lidx + 6] + p[3][lidx + 6]);
        float a7 = (p[0][lidx + 7] + p[1][lidx + 7]) + (p[2][lidx + 7] + p[3][lidx + 7]);
        float se = (a0 + a2) + (a4 + a6);
        float so = (a1 + a3) + (a5 + a7);
        float r  = __fdividef(se - so, fmaxf(se + so, 1e-24f));

        float* ob = out + (size_t)b * (C_OUT * L_OUT) + q * (4 * L_OUT) + l;
        #pragma unroll
        for (int c = 0; c < 4; ++c) {
            ob[c * L_OUT] = cosv[q * 4 + c] * r;
        }
    }
}

extern "C" void kernel_launch(void* const* d_in, const int* in_sizes, int n_in,
                              void* d_out, int out_size)
{
    // Resolve inputs by element count (robust to metadata ordering):
    //   x: 131072, theta: 144, entangle: 262144 (unused)
    const float* x = nullptr;
    const float* theta = nullptr;
    for (int i = 0; i < n_in; ++i) {
        if (in_sizes[i] == BB * C_IN * LL)      x     = (const float*)d_in[i];
        else if (in_sizes[i] == C_OUT * NQ)     theta = (const float*)d_in[i];
    }

    dim3 grid((L_OUT + TL - 1) / TL, BB);   // 8 x 8 = 64 CTAs
    DenseQConv1D_84542136255139_kernel<<<grid, NT>>>(x, theta, (float*)d_out);
}